// round 14
// baseline (speedup 1.0000x reference)
#include <cuda_runtime.h>
#include <stdint.h>

#define TT 3
#define FF 17
#define NN 8
#define DT 0.2f
#define EPS 1e-8f
#define EROW 51                // floats per agent in ego (3*17)
#define NROW 136               // floats per agent in nei (8*17)

// Branchless count of sorted thresholds <= x (k in [0,32]), then 1 FMA.
__device__ __forceinline__ float pwl_eval(const float* __restrict__ t,
                                          const float* __restrict__ A,
                                          const float* __restrict__ C,
                                          float x)
{
    int k = 0;
    if (t[15]    <= x) k  = 16;
    if (t[k + 7] <= x) k += 8;
    if (t[k + 3] <= x) k += 4;
    if (t[k + 1] <= x) k += 2;
    if (t[k]     <= x) k += 1;   // k in [0,31]
    if (t[31]    <= x) k += 1;   // all <= x  => k = 32
    return fmaf(A[k], x, C[k]);
}

struct Tile {
    float g0, g1, g2, g3, g4, g5;
    float a2[8], a3[8], a4[8], a5[8];
};

// R11-proven parity float2 nei loads; scalar ego. Default cache policy
// (L2 retention across graph replays is what the timed loop measures).
__device__ __forceinline__ void load_tile(Tile& T,
    const float* __restrict__ ego, const float* __restrict__ nei, int b)
{
    const float* eg = ego + (size_t)b * EROW + (TT - 1) * FF;
    T.g0 = eg[0]; T.g1 = eg[1]; T.g2 = eg[2];
    T.g3 = eg[3]; T.g4 = eg[4]; T.g5 = eg[5];
    const float* nb = nei + (size_t)b * NROW;
#pragma unroll
    for (int n = 0; n < 8; n++) {
        const float* p = nb + n * FF;
        if (n & 1) {
            T.a2[n] = p[2];
            float2 tv = *reinterpret_cast<const float2*>(p + 3);
            T.a3[n] = tv.x; T.a4[n] = tv.y;
            T.a5[n] = p[5];
        } else {
            float2 tv = *reinterpret_cast<const float2*>(p + 2);
            float2 uv = *reinterpret_cast<const float2*>(p + 4);
            T.a2[n] = tv.x; T.a3[n] = tv.y; T.a4[n] = uv.x; T.a5[n] = uv.y;
        }
    }
}

__device__ __forceinline__ void compute_tile(const Tile& T, int b,
    const float st[3][32], const float sA[3][33], const float sC[3][33],
    const float* sdl, float bd0, float bd3, float p1, float ip0, float effv,
    float* __restrict__ out)
{
    float g2 = T.g2, g3 = T.g3, g4 = T.g4, g5 = T.g5;

    float einv = rsqrtf(g4 * g4 + g5 * g5);
    float ex = g4 * einv, ey = g5 * einv;
    float na = fmaxf(sqrtf(ex * ex + ey * ey), EPS);
    float thr = effv * na;

    float ax = 0.f, ay = 0.f;

    // f_dest: v34 = (g3, g4); dv = (|v34|, 0)
    {
        float nv = sqrtf(g3 * g3 + g4 * g4);
        float fx = (p1 * nv - g3) * ip0;
        float fy = (0.f - g4) * ip0;
        float dot = ex * fx + ey * fy;
        float nbn = fmaxf(sqrtf(fx * fx + fy * fy), EPS);
        bool keep = fabsf(dot) > thr * nbn;
        ax += keep ? fx : 0.f;
        ay += keep ? fy : 0.f;
    }

    // neighbors: attr + repu share direction r -> one keep-test
#pragma unroll
    for (int n = 0; n < 8; n++) {
        bool mx = (T.a2[n] == 0.f), my = (T.a3[n] == 0.f);
        float rx = T.a2[n] - g2, ry = T.a3[n] - g3;
        float rnm = sqrtf(rx * rx + ry * ry);
        float vx = T.a4[n] * DT, vy = T.a5[n] * DT;
        float px = rx + vx, py = ry + vy;
        float bbv = sqrtf(rnm + px * px + py * py - vx * vx - vy * vy) * 0.5f;

        float fa = pwl_eval(st[0], sA[0], sC[0], rnm);   // an
        float fr = pwl_eval(st[1], sA[1], sC[1], bbv);   // rn
        float s = __fdividef(fa * sdl[n] + fr, rnm);

        float fxb = mx ? 0.f : rx;
        float fyb = my ? 0.f : ry;
        float dot = ex * fxb + ey * fyb;
        float nbn = (mx || my) ? sqrtf(fxb * fxb + fyb * fyb) : rnm;
        bool keep = fabsf(dot) > thr * nbn;
        ax += keep ? s * fxb : 0.f;
        ay += keep ? s * fyb : 0.f;
    }

    // f_bor: y-only vectors; rbv/|rbv| == sign(rbv) exactly
    {
        float rbv0 = g3 - bd0;
        float rbv1 = g3 - bd3;
        float rbn0 = fabsf(rbv0), rbn1 = fabsf(rbv1);

        float m0 = pwl_eval(st[2], sA[2], sC[2], rbn0);
        float m1 = pwl_eval(st[2], sA[2], sC[2], rbn1);

        float fy0 = m0 * copysignf(1.f, rbv0);
        float nbn0 = fmaxf(fabsf(fy0), EPS);
        if (fabsf(ey * fy0) > thr * nbn0) ay += fy0;

        float fy1 = m1 * copysignf(1.f, rbv1);
        float nbn1 = fmaxf(fabsf(fy1), EPS);
        if (fabsf(ey * fy1) > thr * nbn1) ay += fy1;
    }

    float vxo = g2 + ax * DT;
    float vyo = g3 + ay * DT;
    float sx = T.g0 + vxo * DT;
    float sy = T.g1 + vyo * DT;

    float2* o = reinterpret_cast<float2*>(out + (size_t)b * 6);
    o[0] = make_float2(sx, sy);
    o[1] = make_float2(vxo, vyo);
    o[2] = make_float2(ax, ay);
}

// ---------------------------------------------------------------------------
// Persistent fused kernel, 512 blocks = one wave at 4/SM, exactly 2 tiles per
// block. Two-tile register pipeline: tile B's loads are issued BEFORE tile A's
// compute, so B's DRAM latency overlaps A's compute. Spills (if any) become
// LDG->STL ... LDL, which preserves the overlap (local is L1-backed).
// ---------------------------------------------------------------------------
__global__ void __launch_bounds__(256, 4) sfm_all(
    const float* __restrict__ ego, const float* __restrict__ nei,
    const float* __restrict__ border, const float* __restrict__ adp,
    const float* __restrict__ eff_angle,
    const float* __restrict__ an_wi, const float* __restrict__ an_bi,
    const float* __restrict__ an_wo, const float* __restrict__ an_bo,
    const float* __restrict__ rn_wi, const float* __restrict__ rn_bi,
    const float* __restrict__ rn_wo, const float* __restrict__ rn_bo,
    const float* __restrict__ rb_wi, const float* __restrict__ rb_bi,
    const float* __restrict__ rb_wo, const float* __restrict__ rb_bo,
    const float* __restrict__ dl_wi, const float* __restrict__ dl_bi,
    const float* __restrict__ dl_wo, const float* __restrict__ dl_bo,
    float* __restrict__ out, int n_batch)
{
    __shared__ float st[3][32];
    __shared__ float sA[3][33];
    __shared__ float sC[3][33];
    __shared__ float sdl[8];

    int tid = threadIdx.x;
    int warp = tid >> 5, lane = tid & 31;
    const unsigned FULL = 0xffffffffu;
    const float PINF = __int_as_float(0x7f800000);

    int tiles = (n_batch + 255) >> 8;

    // ---- preload tile A (overlaps the prologue below) ----
    Tile A, B;
    int t = blockIdx.x;
    bool hasA = (t < tiles);
    int bA = t * 256 + tid;
    bool actA = hasA && (bA < n_batch);
    if (hasA) load_tile(A, ego, nei, actA ? bA : (n_batch - 1));

    // ---- prologue: build tables in-block (same math as before) ----
    if (warp < 3) {
        const float* wi = (warp == 0) ? an_wi : (warp == 1) ? rn_wi : rb_wi;
        const float* bi = (warp == 0) ? an_bi : (warp == 1) ? rn_bi : rb_bi;
        const float* wo = (warp == 0) ? an_wo : (warp == 1) ? rn_wo : rb_wo;
        const float* bo = (warp == 0) ? an_bo : (warp == 1) ? rn_bo : rb_bo;

        float wiv = wi[lane], biv = bi[lane], wov = wo[lane];
        float bov = bo[0];
        // relu(-(wi*x+bi)) active iff x < t  (wi uniform >= 0)
        float tt, slope, icept;
        if (wiv > 0.f) {
            tt = -biv / wiv; slope = -wov * wiv; icept = -wov * biv;
        } else if (biv < 0.f) {
            tt = PINF; slope = 0.f; icept = -wov * biv;   // always active
        } else {
            tt = -PINF; slope = 0.f; icept = 0.f;         // never active
        }

        // rank-sort ascending (ties by lane) via shuffles
        int rank = 0;
#pragma unroll
        for (int i = 0; i < 32; i++) {
            float ti = __shfl_sync(FULL, tt, i);
            rank += (ti < tt) || (ti == tt && i < lane);
        }
        st[warp][rank] = tt;
        sA[warp][rank] = slope;    // scratch
        sC[warp][rank] = icept;    // scratch
        __syncwarp();
        float Av = sA[warp][lane];
        float Cv = sC[warp][lane];
        // inclusive suffix scan: A[k] = sum_{j>=k} slope[j], same for C
#pragma unroll
        for (int off = 1; off < 32; off <<= 1) {
            float a2s = __shfl_down_sync(FULL, Av, off);
            float c2s = __shfl_down_sync(FULL, Cv, off);
            if (lane + off < 32) { Av += a2s; Cv += c2s; }
        }
        Cv += bov;
        __syncwarp();
        sA[warp][lane] = Av;
        sC[warp][lane] = Cv;
        if (lane == 0) { sA[warp][32] = 0.f; sC[warp][32] = bov; }
    } else if (warp == 3 && lane < 8) {
        // dl MLP on dur[n] (depends only on ego batch row 1)
        const float* e1 = ego + (size_t)1 * EROW;
        float id = e1[(TT - 1) * FF + 8 + lane];
        float dur = 0.f;
#pragma unroll
        for (int tq = 0; tq < TT; tq++) {
            bool found = false;
#pragma unroll
            for (int k = 0; k < 8; k++)
                found = found || (e1[tq * FF + 8 + k] == id);
            dur += found ? 1.f : 0.f;
        }
        float acc = dl_bo[0];
#pragma unroll
        for (int j = 0; j < 32; j++) {
            float h = fmaxf(-fmaf(dl_wi[j], dur, dl_bi[j]), 0.f);
            acc = fmaf(dl_wo[j], h, acc);
        }
        sdl[lane] = acc;
    }

    // uniform scalars
    float bd0 = border[0], bd3 = border[3];
    float p0 = adp[0], p1 = adp[1];
    float effv = eff_angle[0];
    float ip0 = __fdividef(1.f, p0);

    __syncthreads();

    // ---- two-tile pipelined persistent loop ----
    while (hasA) {
        int t2 = t + gridDim.x;
        bool hasB = (t2 < tiles);
        int bB = t2 * 256 + tid;
        bool actB = hasB && (bB < n_batch);
        if (hasB) load_tile(B, ego, nei, actB ? bB : (n_batch - 1));

        if (actA) compute_tile(A, bA, st, sA, sC, sdl,
                               bd0, bd3, p1, ip0, effv, out);

        int t3 = t2 + gridDim.x;
        hasA = (t3 < tiles);
        bA = t3 * 256 + tid;
        actA = hasA && (bA < n_batch);
        if (hasA) load_tile(A, ego, nei, actA ? bA : (n_batch - 1));

        if (actB) compute_tile(B, bB, st, sA, sC, sdl,
                               bd0, bd3, p1, ip0, effv, out);

        t = t3;
    }
}

extern "C" void kernel_launch(void* const* d_in, const int* in_sizes, int n_in,
                              void* d_out, int out_size)
{
    const float* ego    = (const float*)d_in[0];
    const float* nei    = (const float*)d_in[1];
    const float* border = (const float*)d_in[2];
    const float* adp    = (const float*)d_in[3];
    const float* eff    = (const float*)d_in[4];
    const float* an_wi  = (const float*)d_in[5];
    const float* an_bi  = (const float*)d_in[6];
    const float* an_wo  = (const float*)d_in[7];
    const float* an_bo  = (const float*)d_in[8];
    const float* rn_wi  = (const float*)d_in[9];
    const float* rn_bi  = (const float*)d_in[10];
    const float* rn_wo  = (const float*)d_in[11];
    const float* rn_bo  = (const float*)d_in[12];
    const float* rb_wi  = (const float*)d_in[13];
    const float* rb_bi  = (const float*)d_in[14];
    const float* rb_wo  = (const float*)d_in[15];
    const float* rb_bo  = (const float*)d_in[16];
    const float* dl_wi  = (const float*)d_in[17];
    const float* dl_bi  = (const float*)d_in[18];
    const float* dl_wo  = (const float*)d_in[19];
    const float* dl_bo  = (const float*)d_in[20];
    float* out = (float*)d_out;

    int n_batch = in_sizes[0] / (TT * FF);
    int tiles = (n_batch + 255) / 256;
    int nblk = tiles < 512 ? tiles : 512;   // one wave at 4/SM x 148 SMs

    sfm_all<<<nblk, 256>>>(ego, nei, border, adp, eff,
                           an_wi, an_bi, an_wo, an_bo,
                           rn_wi, rn_bi, rn_wo, rn_bo,
                           rb_wi, rb_bi, rb_wo, rb_bo,
                           dl_wi, dl_bi, dl_wo, dl_bo,
                           out, n_batch);
}

// round 15
// speedup vs baseline: 1.1805x; 1.1805x over previous
#include <cuda_runtime.h>
#include <stdint.h>

#define TT 3
#define FF 17
#define NN 8
#define DT 0.2f
#define EPS 1e-8f
#define EROW 51                // floats per agent in ego (3*17)
#define NROW 136               // floats per agent in nei (8*17)

// Branchless count of sorted thresholds <= x (k in [0,32]), then 1 FMA.
__device__ __forceinline__ float pwl_eval(const float* __restrict__ t,
                                          const float* __restrict__ A,
                                          const float* __restrict__ C,
                                          float x)
{
    int k = 0;
    if (t[15]    <= x) k  = 16;
    if (t[k + 7] <= x) k += 8;
    if (t[k + 3] <= x) k += 4;
    if (t[k + 1] <= x) k += 2;
    if (t[k]     <= x) k += 1;   // k in [0,31]
    if (t[31]    <= x) k += 1;   // all <= x  => k = 32
    return fmaf(A[k], x, C[k]);
}

__device__ __forceinline__ void prefetch_l2(const void* p) {
    asm volatile("prefetch.global.L2 [%0];" :: "l"(p));
}

// ---------------------------------------------------------------------------
// R13 champion kernel (38.3us) + zero-register L2 prefetch of the NEXT tile
// during the current tile's compute. Persistent 512 blocks = one wave at
// 4/SM; parity float2 nei loads (streaming __ldcs), scalar ego, MUFU divides,
// float2 out stores. Hot-path FP ops unchanged from the validated kernel.
// ---------------------------------------------------------------------------
__global__ void __launch_bounds__(256, 4) sfm_all(
    const float* __restrict__ ego, const float* __restrict__ nei,
    const float* __restrict__ border, const float* __restrict__ adp,
    const float* __restrict__ eff_angle,
    const float* __restrict__ an_wi, const float* __restrict__ an_bi,
    const float* __restrict__ an_wo, const float* __restrict__ an_bo,
    const float* __restrict__ rn_wi, const float* __restrict__ rn_bi,
    const float* __restrict__ rn_wo, const float* __restrict__ rn_bo,
    const float* __restrict__ rb_wi, const float* __restrict__ rb_bi,
    const float* __restrict__ rb_wo, const float* __restrict__ rb_bo,
    const float* __restrict__ dl_wi, const float* __restrict__ dl_bi,
    const float* __restrict__ dl_wo, const float* __restrict__ dl_bo,
    float* __restrict__ out, int n_batch)
{
    __shared__ float st[3][32];
    __shared__ float sA[3][33];
    __shared__ float sC[3][33];
    __shared__ float sdl[8];

    int tid = threadIdx.x;
    int warp = tid >> 5, lane = tid & 31;
    const unsigned FULL = 0xffffffffu;
    const float PINF = __int_as_float(0x7f800000);

    // ---- prologue: build tables in-block (same math as before) ----
    if (warp < 3) {
        const float* wi = (warp == 0) ? an_wi : (warp == 1) ? rn_wi : rb_wi;
        const float* bi = (warp == 0) ? an_bi : (warp == 1) ? rn_bi : rb_bi;
        const float* wo = (warp == 0) ? an_wo : (warp == 1) ? rn_wo : rb_wo;
        const float* bo = (warp == 0) ? an_bo : (warp == 1) ? rn_bo : rb_bo;

        float wiv = wi[lane], biv = bi[lane], wov = wo[lane];
        float bov = bo[0];
        // relu(-(wi*x+bi)) active iff x < t  (wi uniform >= 0)
        float t, slope, icept;
        if (wiv > 0.f) {
            t = -biv / wiv; slope = -wov * wiv; icept = -wov * biv;
        } else if (biv < 0.f) {
            t = PINF; slope = 0.f; icept = -wov * biv;   // always active
        } else {
            t = -PINF; slope = 0.f; icept = 0.f;         // never active
        }

        // rank-sort ascending (ties by lane) via shuffles
        int rank = 0;
#pragma unroll
        for (int i = 0; i < 32; i++) {
            float ti = __shfl_sync(FULL, t, i);
            rank += (ti < t) || (ti == t && i < lane);
        }
        st[warp][rank] = t;
        sA[warp][rank] = slope;    // scratch
        sC[warp][rank] = icept;    // scratch
        __syncwarp();
        float A = sA[warp][lane];
        float C = sC[warp][lane];
        // inclusive suffix scan: A[k] = sum_{j>=k} slope[j], same for C
#pragma unroll
        for (int off = 1; off < 32; off <<= 1) {
            float a2s = __shfl_down_sync(FULL, A, off);
            float c2s = __shfl_down_sync(FULL, C, off);
            if (lane + off < 32) { A += a2s; C += c2s; }
        }
        C += bov;
        __syncwarp();
        sA[warp][lane] = A;
        sC[warp][lane] = C;
        if (lane == 0) { sA[warp][32] = 0.f; sC[warp][32] = bov; }
    } else if (warp == 3 && lane < 8) {
        // dl MLP on dur[n] (depends only on ego batch row 1)
        const float* e1 = ego + (size_t)1 * EROW;
        float id = e1[(TT - 1) * FF + 8 + lane];
        float dur = 0.f;
#pragma unroll
        for (int t = 0; t < TT; t++) {
            bool found = false;
#pragma unroll
            for (int k = 0; k < 8; k++)
                found = found || (e1[t * FF + 8 + k] == id);
            dur += found ? 1.f : 0.f;
        }
        float acc = dl_bo[0];
#pragma unroll
        for (int j = 0; j < 32; j++) {
            float h = fmaxf(-fmaf(dl_wi[j], dur, dl_bi[j]), 0.f);
            acc = fmaf(dl_wo[j], h, acc);
        }
        sdl[lane] = acc;
    }

    // uniform scalars
    float bd0 = border[0], bd3 = border[3];
    float p0 = adp[0], p1 = adp[1];
    float effv = eff_angle[0];
    float ip0 = __fdividef(1.f, p0);

    __syncthreads();

    int tiles = (n_batch + 255) >> 8;

    // ---- persistent tile loop ----
    for (int t = blockIdx.x; t < tiles; t += gridDim.x) {
        int b = t * 256 + tid;
        bool active = (b < n_batch);
        int bl = active ? b : (n_batch - 1);      // clamp: loads stay in-bounds

        // ---- front-batched loads for this tile ----
        const float* eg = ego + (size_t)bl * EROW + (TT - 1) * FF;
        const float* nb = nei + (size_t)bl * NROW;

        float g0 = eg[0], g1 = eg[1], g2 = eg[2],
              g3 = eg[3], g4 = eg[4], g5 = eg[5];

        float a2[8], a3[8], a4[8], a5[8];
#pragma unroll
        for (int n = 0; n < 8; n++) {
            const float* p = nb + n * FF;
            if (n & 1) {
                a2[n] = __ldcs(p + 2);
                float2 tv = __ldcs(reinterpret_cast<const float2*>(p + 3));
                a3[n] = tv.x; a4[n] = tv.y;
                a5[n] = __ldcs(p + 5);
            } else {
                float2 tv = __ldcs(reinterpret_cast<const float2*>(p + 2));
                float2 uv = __ldcs(reinterpret_cast<const float2*>(p + 4));
                a2[n] = tv.x; a3[n] = tv.y; a4[n] = uv.x; a5[n] = uv.y;
            }
        }

        // ---- zero-register L2 prefetch of the NEXT tile's lines ----
        int tn = t + gridDim.x;
        if (tn < tiles) {
            int bn = tn * 256 + tid;
            if (bn >= n_batch) bn = n_batch - 1;
            const float* egN = ego + (size_t)bn * EROW + (TT - 1) * FF;
            const float* nbN = nei + (size_t)bn * NROW;
            prefetch_l2(egN);
#pragma unroll
            for (int n = 0; n < 8; n++)
                prefetch_l2(nbN + n * FF + 2);
        }

        if (active) {
            // ---- compute phase (identical FP ops to R13-validated kernel) ----
            float einv = rsqrtf(g4 * g4 + g5 * g5);
            float ex = g4 * einv, ey = g5 * einv;
            float na = fmaxf(sqrtf(ex * ex + ey * ey), EPS);
            float thr = effv * na;

            float ax = 0.f, ay = 0.f;

            // f_dest: v34 = (g3, g4); dv = (|v34|, 0)
            {
                float nv = sqrtf(g3 * g3 + g4 * g4);
                float fx = (p1 * nv - g3) * ip0;
                float fy = (0.f - g4) * ip0;
                float dot = ex * fx + ey * fy;
                float nbn = fmaxf(sqrtf(fx * fx + fy * fy), EPS);
                bool keep = fabsf(dot) > thr * nbn;
                ax += keep ? fx : 0.f;
                ay += keep ? fy : 0.f;
            }

            // neighbors: attr + repu share direction r -> one keep-test
#pragma unroll
            for (int n = 0; n < 8; n++) {
                bool mx = (a2[n] == 0.f), my = (a3[n] == 0.f);
                float rx = a2[n] - g2, ry = a3[n] - g3;
                float rnm = sqrtf(rx * rx + ry * ry);
                float vx = a4[n] * DT, vy = a5[n] * DT;
                float px = rx + vx, py = ry + vy;
                float bbv = sqrtf(rnm + px * px + py * py - vx * vx - vy * vy) * 0.5f;

                float fa = pwl_eval(st[0], sA[0], sC[0], rnm);   // an
                float fr = pwl_eval(st[1], sA[1], sC[1], bbv);   // rn
                float s = __fdividef(fa * sdl[n] + fr, rnm);

                float fxb = mx ? 0.f : rx;
                float fyb = my ? 0.f : ry;
                float dot = ex * fxb + ey * fyb;
                float nbn = (mx || my) ? sqrtf(fxb * fxb + fyb * fyb) : rnm;
                bool keep = fabsf(dot) > thr * nbn;
                ax += keep ? s * fxb : 0.f;
                ay += keep ? s * fyb : 0.f;
            }

            // f_bor: y-only vectors; rbv/|rbv| == sign(rbv) exactly
            {
                float rbv0 = g3 - bd0;
                float rbv1 = g3 - bd3;
                float rbn0 = fabsf(rbv0), rbn1 = fabsf(rbv1);

                float m0 = pwl_eval(st[2], sA[2], sC[2], rbn0);
                float m1 = pwl_eval(st[2], sA[2], sC[2], rbn1);

                float fy0 = m0 * copysignf(1.f, rbv0);
                float nbn0 = fmaxf(fabsf(fy0), EPS);
                if (fabsf(ey * fy0) > thr * nbn0) ay += fy0;

                float fy1 = m1 * copysignf(1.f, rbv1);
                float nbn1 = fmaxf(fabsf(fy1), EPS);
                if (fabsf(ey * fy1) > thr * nbn1) ay += fy1;
            }

            float vxo = g2 + ax * DT;
            float vyo = g3 + ay * DT;
            float sx = g0 + vxo * DT;
            float sy = g1 + vyo * DT;

            // out: proven float2 stores (24B stride, base 8B aligned), streaming
            float2* o = reinterpret_cast<float2*>(out + (size_t)b * 6);
            __stcs(o + 0, make_float2(sx, sy));
            __stcs(o + 1, make_float2(vxo, vyo));
            __stcs(o + 2, make_float2(ax, ay));
        }
    }
}

extern "C" void kernel_launch(void* const* d_in, const int* in_sizes, int n_in,
                              void* d_out, int out_size)
{
    const float* ego    = (const float*)d_in[0];
    const float* nei    = (const float*)d_in[1];
    const float* border = (const float*)d_in[2];
    const float* adp    = (const float*)d_in[3];
    const float* eff    = (const float*)d_in[4];
    const float* an_wi  = (const float*)d_in[5];
    const float* an_bi  = (const float*)d_in[6];
    const float* an_wo  = (const float*)d_in[7];
    const float* an_bo  = (const float*)d_in[8];
    const float* rn_wi  = (const float*)d_in[9];
    const float* rn_bi  = (const float*)d_in[10];
    const float* rn_wo  = (const float*)d_in[11];
    const float* rn_bo  = (const float*)d_in[12];
    const float* rb_wi  = (const float*)d_in[13];
    const float* rb_bi  = (const float*)d_in[14];
    const float* rb_wo  = (const float*)d_in[15];
    const float* rb_bo  = (const float*)d_in[16];
    const float* dl_wi  = (const float*)d_in[17];
    const float* dl_bi  = (const float*)d_in[18];
    const float* dl_wo  = (const float*)d_in[19];
    const float* dl_bo  = (const float*)d_in[20];
    float* out = (float*)d_out;

    int n_batch = in_sizes[0] / (TT * FF);
    int tiles = (n_batch + 255) / 256;
    int nblk = tiles < 512 ? tiles : 512;   // one wave at 4/SM x 148 SMs

    sfm_all<<<nblk, 256>>>(ego, nei, border, adp, eff,
                           an_wi, an_bi, an_wo, an_bo,
                           rn_wi, rn_bi, rn_wo, rn_bo,
                           rb_wi, rb_bi, rb_wo, rb_bo,
                           dl_wi, dl_bi, dl_wo, dl_bo,
                           out, n_batch);
}

// round 16
// speedup vs baseline: 1.3801x; 1.1691x over previous
#include <cuda_runtime.h>
#include <stdint.h>

#define TT 3
#define FF 17
#define NN 8
#define DT 0.2f
#define EPS 1e-8f
#define EROW 51                // floats per agent in ego (3*17)
#define NROW 136               // floats per agent in nei (8*17)

// Branchless count of sorted thresholds <= x (k in [0,32]), then 1 FMA.
__device__ __forceinline__ float pwl_eval(const float* __restrict__ t,
                                          const float* __restrict__ A,
                                          const float* __restrict__ C,
                                          float x)
{
    int k = 0;
    if (t[15]    <= x) k  = 16;
    if (t[k + 7] <= x) k += 8;
    if (t[k + 3] <= x) k += 4;
    if (t[k + 1] <= x) k += 2;
    if (t[k]     <= x) k += 1;   // k in [0,31]
    if (t[31]    <= x) k += 1;   // all <= x  => k = 32
    return fmaf(A[k], x, C[k]);
}

// ---------------------------------------------------------------------------
// R13 champion kernel (38.3us), byte-identical hot path. Single change:
// grid 512 -> 592 (= 4 blocks/SM x 148 SMs, FULL one-wave residency).
// Load balance: 512-grid gave 68 SMs 8 tiles and 80 SMs 6 tiles (makespan 8);
// 592-grid gives every SM 4 blocks and 6-7 tiles (makespan 7) => ~12% off the
// slowest-SM workload.
// ---------------------------------------------------------------------------
__global__ void __launch_bounds__(256, 4) sfm_all(
    const float* __restrict__ ego, const float* __restrict__ nei,
    const float* __restrict__ border, const float* __restrict__ adp,
    const float* __restrict__ eff_angle,
    const float* __restrict__ an_wi, const float* __restrict__ an_bi,
    const float* __restrict__ an_wo, const float* __restrict__ an_bo,
    const float* __restrict__ rn_wi, const float* __restrict__ rn_bi,
    const float* __restrict__ rn_wo, const float* __restrict__ rn_bo,
    const float* __restrict__ rb_wi, const float* __restrict__ rb_bi,
    const float* __restrict__ rb_wo, const float* __restrict__ rb_bo,
    const float* __restrict__ dl_wi, const float* __restrict__ dl_bi,
    const float* __restrict__ dl_wo, const float* __restrict__ dl_bo,
    float* __restrict__ out, int n_batch)
{
    __shared__ float st[3][32];
    __shared__ float sA[3][33];
    __shared__ float sC[3][33];
    __shared__ float sdl[8];

    int tid = threadIdx.x;
    int warp = tid >> 5, lane = tid & 31;
    const unsigned FULL = 0xffffffffu;
    const float PINF = __int_as_float(0x7f800000);

    // ---- prologue: build tables in-block (same math as before) ----
    if (warp < 3) {
        const float* wi = (warp == 0) ? an_wi : (warp == 1) ? rn_wi : rb_wi;
        const float* bi = (warp == 0) ? an_bi : (warp == 1) ? rn_bi : rb_bi;
        const float* wo = (warp == 0) ? an_wo : (warp == 1) ? rn_wo : rb_wo;
        const float* bo = (warp == 0) ? an_bo : (warp == 1) ? rn_bo : rb_bo;

        float wiv = wi[lane], biv = bi[lane], wov = wo[lane];
        float bov = bo[0];
        // relu(-(wi*x+bi)) active iff x < t  (wi uniform >= 0)
        float t, slope, icept;
        if (wiv > 0.f) {
            t = -biv / wiv; slope = -wov * wiv; icept = -wov * biv;
        } else if (biv < 0.f) {
            t = PINF; slope = 0.f; icept = -wov * biv;   // always active
        } else {
            t = -PINF; slope = 0.f; icept = 0.f;         // never active
        }

        // rank-sort ascending (ties by lane) via shuffles
        int rank = 0;
#pragma unroll
        for (int i = 0; i < 32; i++) {
            float ti = __shfl_sync(FULL, t, i);
            rank += (ti < t) || (ti == t && i < lane);
        }
        st[warp][rank] = t;
        sA[warp][rank] = slope;    // scratch
        sC[warp][rank] = icept;    // scratch
        __syncwarp();
        float A = sA[warp][lane];
        float C = sC[warp][lane];
        // inclusive suffix scan: A[k] = sum_{j>=k} slope[j], same for C
#pragma unroll
        for (int off = 1; off < 32; off <<= 1) {
            float a2s = __shfl_down_sync(FULL, A, off);
            float c2s = __shfl_down_sync(FULL, C, off);
            if (lane + off < 32) { A += a2s; C += c2s; }
        }
        C += bov;
        __syncwarp();
        sA[warp][lane] = A;
        sC[warp][lane] = C;
        if (lane == 0) { sA[warp][32] = 0.f; sC[warp][32] = bov; }
    } else if (warp == 3 && lane < 8) {
        // dl MLP on dur[n] (depends only on ego batch row 1)
        const float* e1 = ego + (size_t)1 * EROW;
        float id = e1[(TT - 1) * FF + 8 + lane];
        float dur = 0.f;
#pragma unroll
        for (int t = 0; t < TT; t++) {
            bool found = false;
#pragma unroll
            for (int k = 0; k < 8; k++)
                found = found || (e1[t * FF + 8 + k] == id);
            dur += found ? 1.f : 0.f;
        }
        float acc = dl_bo[0];
#pragma unroll
        for (int j = 0; j < 32; j++) {
            float h = fmaxf(-fmaf(dl_wi[j], dur, dl_bi[j]), 0.f);
            acc = fmaf(dl_wo[j], h, acc);
        }
        sdl[lane] = acc;
    }

    // uniform scalars
    float bd0 = border[0], bd3 = border[3];
    float p0 = adp[0], p1 = adp[1];
    float effv = eff_angle[0];
    float ip0 = __fdividef(1.f, p0);

    __syncthreads();

    int tiles = (n_batch + 255) >> 8;

    // ---- persistent tile loop ----
    for (int t = blockIdx.x; t < tiles; t += gridDim.x) {
        int b = t * 256 + tid;
        bool active = (b < n_batch);
        int bl = active ? b : (n_batch - 1);      // clamp: loads stay in-bounds

        // ---- front-batched loads for this tile ----
        const float* eg = ego + (size_t)bl * EROW + (TT - 1) * FF;
        const float* nb = nei + (size_t)bl * NROW;

        float g0 = eg[0], g1 = eg[1], g2 = eg[2],
              g3 = eg[3], g4 = eg[4], g5 = eg[5];

        float a2[8], a3[8], a4[8], a5[8];
#pragma unroll
        for (int n = 0; n < 8; n++) {
            const float* p = nb + n * FF;
            if (n & 1) {
                a2[n] = __ldcs(p + 2);
                float2 tv = __ldcs(reinterpret_cast<const float2*>(p + 3));
                a3[n] = tv.x; a4[n] = tv.y;
                a5[n] = __ldcs(p + 5);
            } else {
                float2 tv = __ldcs(reinterpret_cast<const float2*>(p + 2));
                float2 uv = __ldcs(reinterpret_cast<const float2*>(p + 4));
                a2[n] = tv.x; a3[n] = tv.y; a4[n] = uv.x; a5[n] = uv.y;
            }
        }

        if (active) {
            // ---- compute phase (identical FP ops to R13-validated kernel) ----
            float einv = rsqrtf(g4 * g4 + g5 * g5);
            float ex = g4 * einv, ey = g5 * einv;
            float na = fmaxf(sqrtf(ex * ex + ey * ey), EPS);
            float thr = effv * na;

            float ax = 0.f, ay = 0.f;

            // f_dest: v34 = (g3, g4); dv = (|v34|, 0)
            {
                float nv = sqrtf(g3 * g3 + g4 * g4);
                float fx = (p1 * nv - g3) * ip0;
                float fy = (0.f - g4) * ip0;
                float dot = ex * fx + ey * fy;
                float nbn = fmaxf(sqrtf(fx * fx + fy * fy), EPS);
                bool keep = fabsf(dot) > thr * nbn;
                ax += keep ? fx : 0.f;
                ay += keep ? fy : 0.f;
            }

            // neighbors: attr + repu share direction r -> one keep-test
#pragma unroll
            for (int n = 0; n < 8; n++) {
                bool mx = (a2[n] == 0.f), my = (a3[n] == 0.f);
                float rx = a2[n] - g2, ry = a3[n] - g3;
                float rnm = sqrtf(rx * rx + ry * ry);
                float vx = a4[n] * DT, vy = a5[n] * DT;
                float px = rx + vx, py = ry + vy;
                float bbv = sqrtf(rnm + px * px + py * py - vx * vx - vy * vy) * 0.5f;

                float fa = pwl_eval(st[0], sA[0], sC[0], rnm);   // an
                float fr = pwl_eval(st[1], sA[1], sC[1], bbv);   // rn
                float s = __fdividef(fa * sdl[n] + fr, rnm);

                float fxb = mx ? 0.f : rx;
                float fyb = my ? 0.f : ry;
                float dot = ex * fxb + ey * fyb;
                float nbn = (mx || my) ? sqrtf(fxb * fxb + fyb * fyb) : rnm;
                bool keep = fabsf(dot) > thr * nbn;
                ax += keep ? s * fxb : 0.f;
                ay += keep ? s * fyb : 0.f;
            }

            // f_bor: y-only vectors; rbv/|rbv| == sign(rbv) exactly
            {
                float rbv0 = g3 - bd0;
                float rbv1 = g3 - bd3;
                float rbn0 = fabsf(rbv0), rbn1 = fabsf(rbv1);

                float m0 = pwl_eval(st[2], sA[2], sC[2], rbn0);
                float m1 = pwl_eval(st[2], sA[2], sC[2], rbn1);

                float fy0 = m0 * copysignf(1.f, rbv0);
                float nbn0 = fmaxf(fabsf(fy0), EPS);
                if (fabsf(ey * fy0) > thr * nbn0) ay += fy0;

                float fy1 = m1 * copysignf(1.f, rbv1);
                float nbn1 = fmaxf(fabsf(fy1), EPS);
                if (fabsf(ey * fy1) > thr * nbn1) ay += fy1;
            }

            float vxo = g2 + ax * DT;
            float vyo = g3 + ay * DT;
            float sx = g0 + vxo * DT;
            float sy = g1 + vyo * DT;

            // out: proven float2 stores (24B stride, base 8B aligned), streaming
            float2* o = reinterpret_cast<float2*>(out + (size_t)b * 6);
            __stcs(o + 0, make_float2(sx, sy));
            __stcs(o + 1, make_float2(vxo, vyo));
            __stcs(o + 2, make_float2(ax, ay));
        }
    }
}

extern "C" void kernel_launch(void* const* d_in, const int* in_sizes, int n_in,
                              void* d_out, int out_size)
{
    const float* ego    = (const float*)d_in[0];
    const float* nei    = (const float*)d_in[1];
    const float* border = (const float*)d_in[2];
    const float* adp    = (const float*)d_in[3];
    const float* eff    = (const float*)d_in[4];
    const float* an_wi  = (const float*)d_in[5];
    const float* an_bi  = (const float*)d_in[6];
    const float* an_wo  = (const float*)d_in[7];
    const float* an_bo  = (const float*)d_in[8];
    const float* rn_wi  = (const float*)d_in[9];
    const float* rn_bi  = (const float*)d_in[10];
    const float* rn_wo  = (const float*)d_in[11];
    const float* rn_bo  = (const float*)d_in[12];
    const float* rb_wi  = (const float*)d_in[13];
    const float* rb_bi  = (const float*)d_in[14];
    const float* rb_wo  = (const float*)d_in[15];
    const float* rb_bo  = (const float*)d_in[16];
    const float* dl_wi  = (const float*)d_in[17];
    const float* dl_bi  = (const float*)d_in[18];
    const float* dl_wo  = (const float*)d_in[19];
    const float* dl_bo  = (const float*)d_in[20];
    float* out = (float*)d_out;

    int n_batch = in_sizes[0] / (TT * FF);
    int tiles = (n_batch + 255) / 256;
    int nblk = tiles < 592 ? tiles : 592;   // FULL one-wave residency: 4/SM x 148

    sfm_all<<<nblk, 256>>>(ego, nei, border, adp, eff,
                           an_wi, an_bi, an_wo, an_bo,
                           rn_wi, rn_bi, rn_wo, rn_bo,
                           rb_wi, rb_bi, rb_wo, rb_bo,
                           dl_wi, dl_bi, dl_wo, dl_bo,
                           out, n_batch);
}

// round 17
// speedup vs baseline: 1.5117x; 1.0953x over previous
#include <cuda_runtime.h>
#include <stdint.h>

#define TT 3
#define FF 17
#define NN 8
#define DT 0.2f
#define EPS 1e-8f
#define EROW 51                // floats per agent in ego (3*17)
#define NROW 136               // floats per agent in nei (8*17)
#define BLK 128                // threads per block (= agents per tile)

// Branchless count of sorted thresholds <= x (k in [0,32]), then 1 FMA.
__device__ __forceinline__ float pwl_eval(const float* __restrict__ t,
                                          const float* __restrict__ A,
                                          const float* __restrict__ C,
                                          float x)
{
    int k = 0;
    if (t[15]    <= x) k  = 16;
    if (t[k + 7] <= x) k += 8;
    if (t[k + 3] <= x) k += 4;
    if (t[k + 1] <= x) k += 2;
    if (t[k]     <= x) k += 1;   // k in [0,31]
    if (t[31]    <= x) k += 1;   // all <= x  => k = 32
    return fmaf(A[k], x, C[k]);
}

// ---------------------------------------------------------------------------
// R13 champion hot path, repartitioned: 8 blocks/SM x 128 threads instead of
// 4 x 256. Same 32 warps/SM, same instruction stream; independent block
// scheduling desynchronizes load/compute phases across the SM, smoothing the
// DRAM request stream, and the prologue barrier spans exactly the 4 warps
// that build the tables. Persistent grid = 1184 (8 x 148), one full wave.
// ---------------------------------------------------------------------------
__global__ void __launch_bounds__(BLK, 8) sfm_all(
    const float* __restrict__ ego, const float* __restrict__ nei,
    const float* __restrict__ border, const float* __restrict__ adp,
    const float* __restrict__ eff_angle,
    const float* __restrict__ an_wi, const float* __restrict__ an_bi,
    const float* __restrict__ an_wo, const float* __restrict__ an_bo,
    const float* __restrict__ rn_wi, const float* __restrict__ rn_bi,
    const float* __restrict__ rn_wo, const float* __restrict__ rn_bo,
    const float* __restrict__ rb_wi, const float* __restrict__ rb_bi,
    const float* __restrict__ rb_wo, const float* __restrict__ rb_bo,
    const float* __restrict__ dl_wi, const float* __restrict__ dl_bi,
    const float* __restrict__ dl_wo, const float* __restrict__ dl_bo,
    float* __restrict__ out, int n_batch)
{
    __shared__ float st[3][32];
    __shared__ float sA[3][33];
    __shared__ float sC[3][33];
    __shared__ float sdl[8];

    int tid = threadIdx.x;
    int warp = tid >> 5, lane = tid & 31;
    const unsigned FULL = 0xffffffffu;
    const float PINF = __int_as_float(0x7f800000);

    // ---- prologue: build tables in-block (same math as before) ----
    if (warp < 3) {
        const float* wi = (warp == 0) ? an_wi : (warp == 1) ? rn_wi : rb_wi;
        const float* bi = (warp == 0) ? an_bi : (warp == 1) ? rn_bi : rb_bi;
        const float* wo = (warp == 0) ? an_wo : (warp == 1) ? rn_wo : rb_wo;
        const float* bo = (warp == 0) ? an_bo : (warp == 1) ? rn_bo : rb_bo;

        float wiv = wi[lane], biv = bi[lane], wov = wo[lane];
        float bov = bo[0];
        // relu(-(wi*x+bi)) active iff x < t  (wi uniform >= 0)
        float t, slope, icept;
        if (wiv > 0.f) {
            t = -biv / wiv; slope = -wov * wiv; icept = -wov * biv;
        } else if (biv < 0.f) {
            t = PINF; slope = 0.f; icept = -wov * biv;   // always active
        } else {
            t = -PINF; slope = 0.f; icept = 0.f;         // never active
        }

        // rank-sort ascending (ties by lane) via shuffles
        int rank = 0;
#pragma unroll
        for (int i = 0; i < 32; i++) {
            float ti = __shfl_sync(FULL, t, i);
            rank += (ti < t) || (ti == t && i < lane);
        }
        st[warp][rank] = t;
        sA[warp][rank] = slope;    // scratch
        sC[warp][rank] = icept;    // scratch
        __syncwarp();
        float A = sA[warp][lane];
        float C = sC[warp][lane];
        // inclusive suffix scan: A[k] = sum_{j>=k} slope[j], same for C
#pragma unroll
        for (int off = 1; off < 32; off <<= 1) {
            float a2s = __shfl_down_sync(FULL, A, off);
            float c2s = __shfl_down_sync(FULL, C, off);
            if (lane + off < 32) { A += a2s; C += c2s; }
        }
        C += bov;
        __syncwarp();
        sA[warp][lane] = A;
        sC[warp][lane] = C;
        if (lane == 0) { sA[warp][32] = 0.f; sC[warp][32] = bov; }
    } else if (warp == 3 && lane < 8) {
        // dl MLP on dur[n] (depends only on ego batch row 1)
        const float* e1 = ego + (size_t)1 * EROW;
        float id = e1[(TT - 1) * FF + 8 + lane];
        float dur = 0.f;
#pragma unroll
        for (int t = 0; t < TT; t++) {
            bool found = false;
#pragma unroll
            for (int k = 0; k < 8; k++)
                found = found || (e1[t * FF + 8 + k] == id);
            dur += found ? 1.f : 0.f;
        }
        float acc = dl_bo[0];
#pragma unroll
        for (int j = 0; j < 32; j++) {
            float h = fmaxf(-fmaf(dl_wi[j], dur, dl_bi[j]), 0.f);
            acc = fmaf(dl_wo[j], h, acc);
        }
        sdl[lane] = acc;
    }

    // uniform scalars
    float bd0 = border[0], bd3 = border[3];
    float p0 = adp[0], p1 = adp[1];
    float effv = eff_angle[0];
    float ip0 = __fdividef(1.f, p0);

    __syncthreads();

    int tiles = (n_batch + BLK - 1) / BLK;

    // ---- persistent tile loop ----
    for (int t = blockIdx.x; t < tiles; t += gridDim.x) {
        int b = t * BLK + tid;
        bool active = (b < n_batch);
        int bl = active ? b : (n_batch - 1);      // clamp: loads stay in-bounds

        // ---- front-batched loads for this tile ----
        const float* eg = ego + (size_t)bl * EROW + (TT - 1) * FF;
        const float* nb = nei + (size_t)bl * NROW;

        float g0 = eg[0], g1 = eg[1], g2 = eg[2],
              g3 = eg[3], g4 = eg[4], g5 = eg[5];

        float a2[8], a3[8], a4[8], a5[8];
#pragma unroll
        for (int n = 0; n < 8; n++) {
            const float* p = nb + n * FF;
            if (n & 1) {
                a2[n] = __ldcs(p + 2);
                float2 tv = __ldcs(reinterpret_cast<const float2*>(p + 3));
                a3[n] = tv.x; a4[n] = tv.y;
                a5[n] = __ldcs(p + 5);
            } else {
                float2 tv = __ldcs(reinterpret_cast<const float2*>(p + 2));
                float2 uv = __ldcs(reinterpret_cast<const float2*>(p + 4));
                a2[n] = tv.x; a3[n] = tv.y; a4[n] = uv.x; a5[n] = uv.y;
            }
        }

        if (active) {
            // ---- compute phase (identical FP ops to R13-validated kernel) ----
            float einv = rsqrtf(g4 * g4 + g5 * g5);
            float ex = g4 * einv, ey = g5 * einv;
            float na = fmaxf(sqrtf(ex * ex + ey * ey), EPS);
            float thr = effv * na;

            float ax = 0.f, ay = 0.f;

            // f_dest: v34 = (g3, g4); dv = (|v34|, 0)
            {
                float nv = sqrtf(g3 * g3 + g4 * g4);
                float fx = (p1 * nv - g3) * ip0;
                float fy = (0.f - g4) * ip0;
                float dot = ex * fx + ey * fy;
                float nbn = fmaxf(sqrtf(fx * fx + fy * fy), EPS);
                bool keep = fabsf(dot) > thr * nbn;
                ax += keep ? fx : 0.f;
                ay += keep ? fy : 0.f;
            }

            // neighbors: attr + repu share direction r -> one keep-test
#pragma unroll
            for (int n = 0; n < 8; n++) {
                bool mx = (a2[n] == 0.f), my = (a3[n] == 0.f);
                float rx = a2[n] - g2, ry = a3[n] - g3;
                float rnm = sqrtf(rx * rx + ry * ry);
                float vx = a4[n] * DT, vy = a5[n] * DT;
                float px = rx + vx, py = ry + vy;
                float bbv = sqrtf(rnm + px * px + py * py - vx * vx - vy * vy) * 0.5f;

                float fa = pwl_eval(st[0], sA[0], sC[0], rnm);   // an
                float fr = pwl_eval(st[1], sA[1], sC[1], bbv);   // rn
                float s = __fdividef(fa * sdl[n] + fr, rnm);

                float fxb = mx ? 0.f : rx;
                float fyb = my ? 0.f : ry;
                float dot = ex * fxb + ey * fyb;
                float nbn = (mx || my) ? sqrtf(fxb * fxb + fyb * fyb) : rnm;
                bool keep = fabsf(dot) > thr * nbn;
                ax += keep ? s * fxb : 0.f;
                ay += keep ? s * fyb : 0.f;
            }

            // f_bor: y-only vectors; rbv/|rbv| == sign(rbv) exactly
            {
                float rbv0 = g3 - bd0;
                float rbv1 = g3 - bd3;
                float rbn0 = fabsf(rbv0), rbn1 = fabsf(rbv1);

                float m0 = pwl_eval(st[2], sA[2], sC[2], rbn0);
                float m1 = pwl_eval(st[2], sA[2], sC[2], rbn1);

                float fy0 = m0 * copysignf(1.f, rbv0);
                float nbn0 = fmaxf(fabsf(fy0), EPS);
                if (fabsf(ey * fy0) > thr * nbn0) ay += fy0;

                float fy1 = m1 * copysignf(1.f, rbv1);
                float nbn1 = fmaxf(fabsf(fy1), EPS);
                if (fabsf(ey * fy1) > thr * nbn1) ay += fy1;
            }

            float vxo = g2 + ax * DT;
            float vyo = g3 + ay * DT;
            float sx = g0 + vxo * DT;
            float sy = g1 + vyo * DT;

            // out: proven float2 stores (24B stride, base 8B aligned), streaming
            float2* o = reinterpret_cast<float2*>(out + (size_t)b * 6);
            __stcs(o + 0, make_float2(sx, sy));
            __stcs(o + 1, make_float2(vxo, vyo));
            __stcs(o + 2, make_float2(ax, ay));
        }
    }
}

extern "C" void kernel_launch(void* const* d_in, const int* in_sizes, int n_in,
                              void* d_out, int out_size)
{
    const float* ego    = (const float*)d_in[0];
    const float* nei    = (const float*)d_in[1];
    const float* border = (const float*)d_in[2];
    const float* adp    = (const float*)d_in[3];
    const float* eff    = (const float*)d_in[4];
    const float* an_wi  = (const float*)d_in[5];
    const float* an_bi  = (const float*)d_in[6];
    const float* an_wo  = (const float*)d_in[7];
    const float* an_bo  = (const float*)d_in[8];
    const float* rn_wi  = (const float*)d_in[9];
    const float* rn_bi  = (const float*)d_in[10];
    const float* rn_wo  = (const float*)d_in[11];
    const float* rn_bo  = (const float*)d_in[12];
    const float* rb_wi  = (const float*)d_in[13];
    const float* rb_bi  = (const float*)d_in[14];
    const float* rb_wo  = (const float*)d_in[15];
    const float* rb_bo  = (const float*)d_in[16];
    const float* dl_wi  = (const float*)d_in[17];
    const float* dl_bi  = (const float*)d_in[18];
    const float* dl_wo  = (const float*)d_in[19];
    const float* dl_bo  = (const float*)d_in[20];
    float* out = (float*)d_out;

    int n_batch = in_sizes[0] / (TT * FF);
    int tiles = (n_batch + BLK - 1) / BLK;
    int nblk = tiles < 1184 ? tiles : 1184;   // one wave: 8 blocks/SM x 148 SMs

    sfm_all<<<nblk, BLK>>>(ego, nei, border, adp, eff,
                           an_wi, an_bi, an_wo, an_bo,
                           rn_wi, rn_bi, rn_wo, rn_bo,
                           rb_wi, rb_bi, rb_wo, rb_bo,
                           dl_wi, dl_bi, dl_wo, dl_bo,
                           out, n_batch);
}